// round 16
// baseline (speedup 1.0000x reference)
#include <cuda_runtime.h>
#include <cuda_fp16.h>
#include <math.h>
#include <stdint.h>

#define T_DIM 500
#define B_DIM 32
#define U_DIM 100
#define I_DIM 1024
#define E_DIM 512
#define M_DIM 512
#define C_DIM 1024
#define O_DIM 512
#define G_DIM 4096
#define NUM_CLASS 5000

// ---------------- scratch (device globals) -----------------------------------
__device__ __align__(16) uint32_t g_wt[G_DIM / 16 * 2048 / 8 * 32 * 4];  // packed W frags
__device__ __align__(16) uint32_t g_dt[16000 / 16 * 1024 / 8 * 32 * 4]; // packed data frags
__device__ __align__(16) uint32_t g_bt[1024 / 8 * 512 / 8 * 32 * 2];    // packed Wi2h frags
__device__ __align__(16) uint32_t g_xemb[U_DIM * 64 * 4 * 32 * 2];      // packed emb frags
__device__ __align__(16) uint32_t g_xt[256 * 4 * 32 * 2];               // packed x frags (ctx+p)
__device__ __half g_att_hh[T_DIM * B_DIM * M_DIM];   // [t*32+b][m] fp16 (L2 fit!)
__device__ float g_gpart[4 * G_DIM * B_DIM];         // [ky][j][b]
__device__ float g_ppart[8 * O_DIM * B_DIM];         // [ky][r][b]
__device__ float g_spart[16 * M_DIM * B_DIM];        // [ksp][m][b]
__device__ float g_c[2][C_DIM * B_DIM];              // double-buffered cell state
__device__ float g_cpart[4 * B_DIM * I_DIM];         // [chunk][b*1024+i]
__device__ int   g_ctr[32];                          // per-b ctx counters (monotonic)
__device__ unsigned g_barA;                          // global barrier (monotonic)

__device__ __forceinline__ float fast_tanh(float x) {
    float y; asm("tanh.approx.f32 %0, %1;" : "=f"(y) : "f"(x)); return y;
}
__device__ __forceinline__ float sigf(float x) { return 1.0f / (1.0f + expf(-x)); }
__device__ __forceinline__ uint32_t f2tf(float v) {
    uint32_t r; asm("cvt.rna.tf32.f32 %0, %1;" : "=r"(r) : "f"(v)); return r;
}
__device__ __forceinline__ void mma8(float& d0, float& d1, float& d2, float& d3,
                                     uint32_t a0, uint32_t a1, uint32_t a2, uint32_t a3,
                                     uint32_t b0, uint32_t b1) {
    asm("mma.sync.aligned.m16n8k8.row.col.f32.tf32.tf32.f32 "
        "{%0,%1,%2,%3},{%4,%5,%6,%7},{%8,%9},{%0,%1,%2,%3};"
        : "+f"(d0), "+f"(d1), "+f"(d2), "+f"(d3)
        : "r"(a0), "r"(a1), "r"(a2), "r"(a3), "r"(b0), "r"(b1));
}

// monotonic global barrier; all 128 blocks co-resident (grid 128 <= 148 SMs)
__device__ __forceinline__ void gbar(unsigned target) {
    __syncthreads();
    if (threadIdx.x == 0) {
        __threadfence();
        atomicAdd(&g_barA, 1u);
        while (atomicAdd(&g_barA, 0u) < target) __nanosleep(32);
        __threadfence();
    }
    __syncthreads();
}

// ---------------- pack W = [Wx | Wp] into A-fragment layout -------------------
__global__ void k_wpack(const float* __restrict__ Wx, const float* __restrict__ Wp) {
    int idx = blockIdx.x * 256 + threadIdx.x;        // 8,388,608
    int r = idx & 3, lane = (idx >> 2) & 31, kt = (idx >> 7) & 255, mt = idx >> 15;
    int j = mt * 16 + (lane >> 2) + (r & 1) * 8;
    int k = kt * 8 + (lane & 3) + (r >> 1) * 4;
    float v = (k < 1536) ? Wx[j * 1536 + k] : Wp[j * 512 + (k - 1536)];
    g_wt[idx] = f2tf(v);
}

// ---------------- pack data into A-fragment layout ----------------------------
__global__ void k_dpack(const float* __restrict__ data) {
    int idx = blockIdx.x * 256 + threadIdx.x;        // 16,384,000
    int r = idx & 3, lane = (idx >> 2) & 31, kt = (idx >> 7) & 127, mt = idx >> 14;
    int m = mt * 16 + (lane >> 2) + (r & 1) * 8;
    int k = kt * 8 + (lane & 3) + (r >> 1) * 4;
    g_dt[idx] = f2tf(data[m * 1024 + k]);
}

// ---------------- pack Wi2h into B-fragment layout ----------------------------
__global__ void k_bpack(const float* __restrict__ Wi2h) {
    int idx = blockIdx.x * 256 + threadIdx.x;        // 524,288
    int r = idx & 1, lane = (idx >> 1) & 31, nt = (idx >> 6) & 63, kt = idx >> 12;
    int k = kt * 8 + (lane & 3) + r * 4;
    int n = nt * 8 + (lane >> 2);
    g_bt[idx] = f2tf(Wi2h[n * 1024 + k]);
}

// ---------------- embedding -> packed B fragments per u ------------------------
__global__ void k_embed(const int* __restrict__ label, const float* __restrict__ embW) {
    int idx = blockIdx.x * 256 + threadIdx.x;        // 1,638,400
    int r = idx & 1, lane = (idx >> 1) & 31, nt = (idx >> 6) & 3, kt = (idx >> 8) & 63, u = idx >> 14;
    int e = kt * 8 + (lane & 3) + r * 4;
    int b = nt * 8 + (lane >> 2);
    int lab = (u == 0) ? (NUM_CLASS - 2) : label[(u - 1) * B_DIM + b];
    float v = 0.0f;
    if (lab >= 0) v = embW[lab * E_DIM + e];
    g_xemb[idx] = f2tf(v);
}

// ---------------- init: zero c buf0, packed x, barrier + counters --------------
__global__ void k_init() {
    int idx = blockIdx.x * 256 + threadIdx.x;        // 65536
    if (idx < C_DIM * B_DIM) g_c[0][idx] = 0.0f;
    if (idx < 65536) g_xt[idx] = 0u;
    if (idx < 32) g_ctr[idx] = 0;
    if (idx == 0) g_barA = 0u;
}

// ---------------- att_h via tf32 mma, stored fp16 ------------------------------
__global__ void __launch_bounds__(512) k_atth(void) {
    int tid = threadIdx.x;
    int lane = tid & 31, wid = tid >> 5;
    int wm = wid & 7, wn = wid >> 3;
    int mt = blockIdx.x * 8 + wm;
    int ntb = blockIdx.y * 16 + wn * 8;

    float d[8][4];
#pragma unroll
    for (int n = 0; n < 8; n++)
#pragma unroll
        for (int c = 0; c < 4; c++) d[n][c] = 0.0f;

    const uint4* ap = reinterpret_cast<const uint4*>(g_dt) + (mt * 128) * 32 + lane;
    const uint2* bp = reinterpret_cast<const uint2*>(g_bt) + ntb * 32 + lane;
#pragma unroll 2
    for (int kt = 0; kt < 128; kt++) {
        uint4 a = ap[kt * 32];
#pragma unroll
        for (int n = 0; n < 8; n++) {
            uint2 b = bp[(kt * 64 + n) * 32];
            mma8(d[n][0], d[n][1], d[n][2], d[n][3], a.x, a.y, a.z, a.w, b.x, b.y);
        }
    }
    int gid = lane >> 2, tig = lane & 3;
    int m0 = mt * 16 + gid;
#pragma unroll
    for (int n = 0; n < 8; n++) {
        int nn = (ntb + n) * 8 + 2 * tig;        // even -> half2-aligned
        *(__half2*)&g_att_hh[m0 * 512 + nn]       = __floats2half2_rn(d[n][0], d[n][1]);
        *(__half2*)&g_att_hh[(m0 + 8) * 512 + nn] = __floats2half2_rn(d[n][2], d[n][3]);
    }
}

// ================ persistent mega-kernel: all 100 steps =========================
// 128 blocks x 256 threads, 64KB dyn smem -> 1 block/SM, all wave-1 resident.
__global__ void __launch_bounds__(256) k_mega(const float* __restrict__ Wproj,
                                              const float* __restrict__ bias,
                                              const float* __restrict__ Wp2s,
                                              const float* __restrict__ attm,
                                              const float* __restrict__ data,
                                              const float* __restrict__ rnn_mask,
                                              const float* __restrict__ wv,
                                              float* __restrict__ out) {
    extern __shared__ char smA[];
    __shared__ int isLast;
    int tid = threadIdx.x;
    int lane = tid & 31, wid = tid >> 5;
    int blk = blockIdx.x;

#pragma unroll 1
    for (int u = 0; u < U_DIM; u++) {
        unsigned base = (unsigned)u * 512u;

        // ---------- phase 1: gates mma (all 128 blocks: 32 x-blocks x 4 ky) ----
        {
            uint2* bsm = (uint2*)smA;                // 64 KB
            int x = blk & 31, ky = blk >> 5;
            int mt = x * 8 + wid;
            const uint2* bsrc = (ky == 0)
                ? reinterpret_cast<const uint2*>(g_xemb) + u * 8192
                : reinterpret_cast<const uint2*>(g_xt) + ky * 8192;
#pragma unroll 8
            for (int q = 0; q < 32; q++) bsm[q * 256 + tid] = __ldcg(&bsrc[q * 256 + tid]);
            __syncthreads();

            float d[4][4];
#pragma unroll
            for (int n = 0; n < 4; n++)
#pragma unroll
                for (int c = 0; c < 4; c++) d[n][c] = 0.0f;

            const uint4* ap = reinterpret_cast<const uint4*>(g_wt) + (mt * 256 + ky * 64) * 32 + lane;
#pragma unroll 4
            for (int kt = 0; kt < 64; kt++) {
                uint4 a = ap[kt * 32];
#pragma unroll
                for (int n = 0; n < 4; n++) {
                    uint2 b = bsm[(kt * 4 + n) * 32 + lane];
                    mma8(d[n][0], d[n][1], d[n][2], d[n][3], a.x, a.y, a.z, a.w, b.x, b.y);
                }
            }
            int gid = lane >> 2, tig = lane & 3;
            int j0 = mt * 16 + gid;
            float* gp = g_gpart + ky * (G_DIM * 32);
#pragma unroll
            for (int n = 0; n < 4; n++) {
                int bb = n * 8 + 2 * tig;
                *(float2*)&gp[j0 * 32 + bb]       = make_float2(d[n][0], d[n][1]);
                *(float2*)&gp[(j0 + 8) * 32 + bb] = make_float2(d[n][2], d[n][3]);
            }
        }
        gbar(base + 128);

        // ---------- phase 2: fused LSTM + proj partials (blocks 0..63) ---------
        if (blk < 64) {
            float* Wsm = (float*)smA;                // 16 KB
            float* xsm = (float*)(smA + 16384);      // 128*33*4
            int ky = blk >> 3;
            int row0 = (blk & 7) * 64;
            const float* cold = g_c[u & 1];
            float* cnew = g_c[(u + 1) & 1];

#pragma unroll 4
            for (int q = 0; q < 16; q++) {
                int idx = q * 256 + tid;
                int k = idx >> 5, b = idx & 31;
                int ci = ky * 128 + k;
                float gt[4];
#pragma unroll
                for (int gi = 0; gi < 4; gi++) {
                    int j = gi * 1024 + ci;
                    float s = __ldg(&bias[j]);
                    s += __ldcg(&g_gpart[j * 32 + b]);
                    s += __ldcg(&g_gpart[131072 + j * 32 + b]);
                    s += __ldcg(&g_gpart[262144 + j * 32 + b]);
                    s += __ldcg(&g_gpart[393216 + j * 32 + b]);
                    gt[gi] = s;
                }
                float c = __ldcg(&cold[ci * 32 + b]);
                c = sigf(gt[1]) * c + sigf(gt[0]) * tanhf(gt[2]);
                c = fminf(fmaxf(c, -1.0f), 1.0f);
                float h = sigf(gt[3]) * tanhf(c);
                xsm[k * 33 + b] = h;
                if ((blk & 7) == 0) cnew[ci * 32 + b] = c;
            }

            const float* wsrc = Wproj + ky * 128;
            float4 wr[4];
#pragma unroll
            for (int q = 0; q < 4; q++) {
                int idx = q * 256 + tid; int r = idx >> 4, c = (idx & 15) * 4;
                wr[q] = *(const float4*)&wsrc[(row0 + r) * 1024 + c];
            }
            float acc[8];
#pragma unroll
            for (int r = 0; r < 8; r++) acc[r] = 0.0f;

            for (int sub = 0; sub < 2; sub++) {
                __syncthreads();
#pragma unroll
                for (int q = 0; q < 4; q++) {
                    int idx = q * 256 + tid; int r = idx >> 4, c = (idx & 15) * 4;
                    *(float4*)&Wsm[r * 64 + c] = wr[q];
                }
                __syncthreads();
                if (sub < 1) {
#pragma unroll
                    for (int q = 0; q < 4; q++) {
                        int idx = q * 256 + tid; int r = idx >> 4, c = (idx & 15) * 4;
                        wr[q] = *(const float4*)&wsrc[(row0 + r) * 1024 + 64 + c];
                    }
                }
#pragma unroll 4
                for (int kk = 0; kk < 64; kk += 4) {
                    int kb = sub * 64 + kk;
                    float x0 = xsm[kb * 33 + lane];
                    float x1 = xsm[(kb + 1) * 33 + lane];
                    float x2 = xsm[(kb + 2) * 33 + lane];
                    float x3 = xsm[(kb + 3) * 33 + lane];
#pragma unroll
                    for (int r = 0; r < 8; r++) {
                        float4 wv4 = *(const float4*)&Wsm[(wid * 8 + r) * 64 + kk];
                        acc[r] += wv4.x * x0 + wv4.y * x1 + wv4.z * x2 + wv4.w * x3;
                    }
                }
            }
#pragma unroll
            for (int r = 0; r < 8; r++) {
                int j = row0 + wid * 8 + r;
                g_ppart[ky * (O_DIM * 32) + j * 32 + lane] = acc[r];
            }
        }
        gbar(base + 256);

        // ---------- phase 3: state partials (128 blocks: 8 mrow x 16 ksplit) ---
        {
            float* psm  = (float*)smA;               // 32*33 floats
            float* Wsm3 = (float*)(smA + 4224);      // 64*33 floats
            int mrow = blk >> 4, ksp = blk & 15;
            int k0 = ksp * 32;

#pragma unroll
            for (int q = 0; q < 4; q++) {
                int idx = q * 256 + tid; int rl = idx >> 5, b = idx & 31;
                float s = 0.0f;
#pragma unroll
                for (int ky = 0; ky < 8; ky++)
                    s += __ldcg(&g_ppart[ky * (O_DIM * 32) + (k0 + rl) * 32 + b]);
                psm[rl * 33 + b] = s;
                if (mrow == 0) {                     // packed p + masked lstmp out
                    int k = k0 + rl;
                    int kt = 192 + (k >> 3), reg = (k >> 2) & 1, ln = (b & 7) * 4 + (k & 3);
                    g_xt[((kt * 4 + (b >> 3)) * 32 + ln) * 2 + reg] = f2tf(s);
                    out[u * (B_DIM * 1536) + b * 1536 + k] = s * attm[u * 32 + b];
                }
            }
#pragma unroll
            for (int q = 0; q < 8; q++) {
                int idx = q * 256 + tid; int r = idx >> 5, c = idx & 31;
                Wsm3[r * 33 + c] = Wp2s[(mrow * 64 + r) * 512 + k0 + c];
            }
            __syncthreads();

            float acc[8];
#pragma unroll
            for (int r = 0; r < 8; r++) acc[r] = 0.0f;
#pragma unroll 8
            for (int rl = 0; rl < 32; rl++) {
                float x = psm[rl * 33 + lane];
#pragma unroll
                for (int r = 0; r < 8; r++)
                    acc[r] += Wsm3[(wid * 8 + r) * 33 + rl] * x;
            }
#pragma unroll
            for (int r = 0; r < 8; r++) {
                int m = mrow * 64 + wid * 8 + r;
                g_spart[ksp * (M_DIM * 32) + m * 32 + lane] = acc[r];
            }
        }
        gbar(base + 384);

        // ---------- phase 4: scalars + ctx (128 blocks: 32 b x 4 chunks) -------
        {
            float* stt = (float*)smA;                // 512
            float* wvs = (float*)(smA + 2048);       // 512
            float* ssm = (float*)(smA + 4096);       // 125
            int b = blk >> 2, chunk = blk & 3;
            int t0 = chunk * 125;

#pragma unroll
            for (int q = 0; q < 2; q++) {            // state[b][m] from 16 partials
                int m = q * 256 + tid;
                float s = 0.0f;
#pragma unroll
                for (int ksp = 0; ksp < 16; ksp++)
                    s += __ldcg(&g_spart[ksp * (M_DIM * 32) + m * 32 + b]);
                stt[m] = s;
            }
#pragma unroll
            for (int m = tid; m < 512; m += 256) wvs[m] = wv[m];
            __syncthreads();

            for (int t = t0 + wid; t < t0 + 125; t += 8) {
                const __half2* ah2 = (const __half2*)&g_att_hh[(t * 32 + b) * 512];
                float s = 0.0f;
#pragma unroll
                for (int it = 0; it < 8; it++) {
                    int p = lane + it * 32;          // pair index 0..255
                    float2 f = __half22float2(ah2[p]);
                    int m = 2 * p;
                    s += wvs[m]     * fast_tanh(stt[m]     + f.x);
                    s += wvs[m + 1] * fast_tanh(stt[m + 1] + f.y);
                }
#pragma unroll
                for (int off = 16; off; off >>= 1) s += __shfl_xor_sync(0xffffffffu, s, off);
                if (lane == 0) {
                    float bv = (rnn_mask[t * 32 + b] - 1.0f) * 1e10f;
                    ssm[t - t0] = 1.0f / (1.0f + __expf(-(s + bv)));
                }
            }
            __syncthreads();

            const float* dbase = data + (size_t)t0 * 32768 + b * 1024 + tid * 4;
            float4 a4 = make_float4(0.f, 0.f, 0.f, 0.f);
            for (int tt = 0; tt < 125; tt += 5) {
                float4 v[5];
#pragma unroll
                for (int j = 0; j < 5; j++)
                    v[j] = __ldcg((const float4*)(dbase + (size_t)(tt + j) * 32768));
#pragma unroll
                for (int j = 0; j < 5; j++) {
                    float sc = ssm[tt + j];
                    a4.x += v[j].x * sc; a4.y += v[j].y * sc;
                    a4.z += v[j].z * sc; a4.w += v[j].w * sc;
                }
            }
            *(float4*)&g_cpart[chunk * 32768 + b * 1024 + tid * 4] = a4;

            __syncthreads();                         // all stores before fence
            if (tid == 0) {
                __threadfence();
                int old = atomicAdd(&g_ctr[b], 1);
                isLast = (old == u * 4 + 3);         // monotonic per replay
            }
            __syncthreads();
            if (isLast) {
                __threadfence();
                float4 s4 = make_float4(0.f, 0.f, 0.f, 0.f);
#pragma unroll
                for (int p = 0; p < 4; p++) {
                    float4 v = __ldcg((const float4*)&g_cpart[p * 32768 + b * 1024 + tid * 4]);
                    s4.x += v.x; s4.y += v.y; s4.z += v.z; s4.w += v.w;
                }
                float sv[4] = {s4.x, s4.y, s4.z, s4.w};
#pragma unroll
                for (int c = 0; c < 4; c++) {
                    int i = tid * 4 + c;
                    int kt = 64 + (i >> 3), ln = (b & 7) * 4 + (i & 3), reg = (i >> 2) & 1;
                    g_xt[((kt * 4 + (b >> 3)) * 32 + ln) * 2 + reg] = f2tf(sv[c]);
                    out[u * (B_DIM * 1536) + b * 1536 + 512 + i] = sv[c] * attm[u * 32 + b];
                }
            }
        }
        gbar(base + 512);   // g_xt complete before next step's gates
    }
}

// ---------------- launch --------------------------------------------------------
extern "C" void kernel_launch(void* const* d_in, const int* in_sizes, int n_in,
                              void* d_out, int out_size) {
    const float* data      = (const float*)d_in[0];
    const float* att_mask  = (const float*)d_in[1];
    const int*   att_label = (const int*)  d_in[2];
    const float* rnn_mask  = (const float*)d_in[3];
    const float* embW      = (const float*)d_in[4];
    const float* Wi2h      = (const float*)d_in[5];
    const float* Wp2s      = (const float*)d_in[6];
    const float* wv        = (const float*)d_in[7];
    const float* Wx        = (const float*)d_in[8];
    const float* Wp        = (const float*)d_in[9];
    const float* bias      = (const float*)d_in[10];
    const float* Wproj     = (const float*)d_in[11];
    float* out = (float*)d_out;

    cudaFuncSetAttribute(k_mega, cudaFuncAttributeMaxDynamicSharedMemorySize, 65536);

    k_wpack<<<32768, 256>>>(Wx, Wp);
    k_dpack<<<64000, 256>>>(data);
    k_bpack<<<2048, 256>>>(Wi2h);
    k_embed<<<6400, 256>>>(att_label, embW);
    k_atth<<<dim3(125, 4), 512>>>();
    k_init<<<256, 256>>>();

    k_mega<<<128, 256, 65536>>>(Wproj, bias, Wp2s, att_mask, data,
                                rnn_mask, wv, out);
}

// round 17
// speedup vs baseline: 1.2656x; 1.2656x over previous
#include <cuda_runtime.h>
#include <cuda_fp16.h>
#include <math.h>
#include <stdint.h>

#define T_DIM 500
#define B_DIM 32
#define U_DIM 100
#define I_DIM 1024
#define E_DIM 512
#define M_DIM 512
#define C_DIM 1024
#define O_DIM 512
#define G_DIM 4096
#define NUM_CLASS 5000

// ---------------- scratch (device globals) -----------------------------------
__device__ __align__(16) uint32_t g_wt[G_DIM / 16 * 2048 / 8 * 32 * 4];  // packed W frags
__device__ __align__(16) uint32_t g_dt[16000 / 16 * 1024 / 8 * 32 * 4]; // packed data frags
__device__ __align__(16) uint32_t g_bt[1024 / 8 * 512 / 8 * 32 * 2];    // packed Wi2h frags
__device__ __align__(16) uint32_t g_xemb[U_DIM * 64 * 4 * 32 * 2];      // packed emb frags
__device__ __align__(16) uint32_t g_xt[256 * 4 * 32 * 2];               // packed x frags (ctx+p)
__device__ __align__(16) __half g_att_hh[T_DIM * B_DIM * M_DIM];        // fp16 att_h (16.4MB)
__device__ __align__(16) __half g_datah[T_DIM * B_DIM * I_DIM];         // fp16 data  (32.7MB)
__device__ float g_gpart[4 * G_DIM * B_DIM];         // [ky][j][b]
__device__ float g_ppart[8 * O_DIM * B_DIM];         // [ky][r][b]
__device__ float g_spart[16 * M_DIM * B_DIM];        // [ksp][m][b]
__device__ float g_c[2][C_DIM * B_DIM];              // double-buffered cell state
__device__ float g_cpart[4 * B_DIM * I_DIM];         // [chunk][b*1024+i]
__device__ int   g_ctr[32];                          // per-b ctx counters (monotonic)
__device__ unsigned g_barA;                          // global barrier (monotonic)

__device__ __forceinline__ float fast_tanh(float x) {
    float y; asm("tanh.approx.f32 %0, %1;" : "=f"(y) : "f"(x)); return y;
}
__device__ __forceinline__ float sigf(float x) { return 1.0f / (1.0f + expf(-x)); }
__device__ __forceinline__ uint32_t f2tf(float v) {
    uint32_t r; asm("cvt.rna.tf32.f32 %0, %1;" : "=r"(r) : "f"(v)); return r;
}
__device__ __forceinline__ void mma8(float& d0, float& d1, float& d2, float& d3,
                                     uint32_t a0, uint32_t a1, uint32_t a2, uint32_t a3,
                                     uint32_t b0, uint32_t b1) {
    asm("mma.sync.aligned.m16n8k8.row.col.f32.tf32.tf32.f32 "
        "{%0,%1,%2,%3},{%4,%5,%6,%7},{%8,%9},{%0,%1,%2,%3};"
        : "+f"(d0), "+f"(d1), "+f"(d2), "+f"(d3)
        : "r"(a0), "r"(a1), "r"(a2), "r"(a3), "r"(b0), "r"(b1));
}

// monotonic global barrier; all 128 blocks co-resident (grid 128 <= 148 SMs)
__device__ __forceinline__ void gbar(unsigned target) {
    __syncthreads();
    if (threadIdx.x == 0) {
        __threadfence();
        atomicAdd(&g_barA, 1u);
        while (atomicAdd(&g_barA, 0u) < target) __nanosleep(32);
        __threadfence();
    }
    __syncthreads();
}

// ---------------- pack W = [Wx | Wp] into A-fragment layout -------------------
__global__ void k_wpack(const float* __restrict__ Wx, const float* __restrict__ Wp) {
    int idx = blockIdx.x * 256 + threadIdx.x;        // 8,388,608
    int r = idx & 3, lane = (idx >> 2) & 31, kt = (idx >> 7) & 255, mt = idx >> 15;
    int j = mt * 16 + (lane >> 2) + (r & 1) * 8;
    int k = kt * 8 + (lane & 3) + (r >> 1) * 4;
    float v = (k < 1536) ? Wx[j * 1536 + k] : Wp[j * 512 + (k - 1536)];
    g_wt[idx] = f2tf(v);
}

// ---------------- pack data into A-fragment layout ----------------------------
__global__ void k_dpack(const float* __restrict__ data) {
    int idx = blockIdx.x * 256 + threadIdx.x;        // 16,384,000
    int r = idx & 3, lane = (idx >> 2) & 31, kt = (idx >> 7) & 127, mt = idx >> 14;
    int m = mt * 16 + (lane >> 2) + (r & 1) * 8;
    int k = kt * 8 + (lane & 3) + (r >> 1) * 4;
    g_dt[idx] = f2tf(data[m * 1024 + k]);
}

// ---------------- pack data into fp16 (same layout) ----------------------------
__global__ void k_hpack(const float* __restrict__ data) {
    int idx = blockIdx.x * 256 + threadIdx.x;        // 16,384,000
    g_datah[idx] = __float2half_rn(data[idx]);
}

// ---------------- pack Wi2h into B-fragment layout ----------------------------
__global__ void k_bpack(const float* __restrict__ Wi2h) {
    int idx = blockIdx.x * 256 + threadIdx.x;        // 524,288
    int r = idx & 1, lane = (idx >> 1) & 31, nt = (idx >> 6) & 63, kt = idx >> 12;
    int k = kt * 8 + (lane & 3) + r * 4;
    int n = nt * 8 + (lane >> 2);
    g_bt[idx] = f2tf(Wi2h[n * 1024 + k]);
}

// ---------------- embedding -> packed B fragments per u ------------------------
__global__ void k_embed(const int* __restrict__ label, const float* __restrict__ embW) {
    int idx = blockIdx.x * 256 + threadIdx.x;        // 1,638,400
    int r = idx & 1, lane = (idx >> 1) & 31, nt = (idx >> 6) & 3, kt = (idx >> 8) & 63, u = idx >> 14;
    int e = kt * 8 + (lane & 3) + r * 4;
    int b = nt * 8 + (lane >> 2);
    int lab = (u == 0) ? (NUM_CLASS - 2) : label[(u - 1) * B_DIM + b];
    float v = 0.0f;
    if (lab >= 0) v = embW[lab * E_DIM + e];
    g_xemb[idx] = f2tf(v);
}

// ---------------- init: zero c buf0, packed x, barrier + counters --------------
__global__ void k_init() {
    int idx = blockIdx.x * 256 + threadIdx.x;        // 65536
    if (idx < C_DIM * B_DIM) g_c[0][idx] = 0.0f;
    if (idx < 65536) g_xt[idx] = 0u;
    if (idx < 32) g_ctr[idx] = 0;
    if (idx == 0) g_barA = 0u;
}

// ---------------- att_h via tf32 mma, stored fp16 ------------------------------
__global__ void __launch_bounds__(512) k_atth(void) {
    int tid = threadIdx.x;
    int lane = tid & 31, wid = tid >> 5;
    int wm = wid & 7, wn = wid >> 3;
    int mt = blockIdx.x * 8 + wm;
    int ntb = blockIdx.y * 16 + wn * 8;

    float d[8][4];
#pragma unroll
    for (int n = 0; n < 8; n++)
#pragma unroll
        for (int c = 0; c < 4; c++) d[n][c] = 0.0f;

    const uint4* ap = reinterpret_cast<const uint4*>(g_dt) + (mt * 128) * 32 + lane;
    const uint2* bp = reinterpret_cast<const uint2*>(g_bt) + ntb * 32 + lane;
#pragma unroll 2
    for (int kt = 0; kt < 128; kt++) {
        uint4 a = ap[kt * 32];
#pragma unroll
        for (int n = 0; n < 8; n++) {
            uint2 b = bp[(kt * 64 + n) * 32];
            mma8(d[n][0], d[n][1], d[n][2], d[n][3], a.x, a.y, a.z, a.w, b.x, b.y);
        }
    }
    int gid = lane >> 2, tig = lane & 3;
    int m0 = mt * 16 + gid;
#pragma unroll
    for (int n = 0; n < 8; n++) {
        int nn = (ntb + n) * 8 + 2 * tig;        // even -> half2-aligned
        *(__half2*)&g_att_hh[m0 * 512 + nn]       = __floats2half2_rn(d[n][0], d[n][1]);
        *(__half2*)&g_att_hh[(m0 + 8) * 512 + nn] = __floats2half2_rn(d[n][2], d[n][3]);
    }
}

// ================ persistent mega-kernel: all 100 steps =========================
// 128 blocks x 256 threads, 64KB dyn smem -> 1 block/SM, all wave-1 resident.
// All mutable cross-block buffers read via __ldcg (no per-launch L1 flush here).
__global__ void __launch_bounds__(256) k_mega(const float* __restrict__ Wproj,
                                              const float* __restrict__ bias,
                                              const float* __restrict__ Wp2s,
                                              const float* __restrict__ attm,
                                              const float* __restrict__ rnn_mask,
                                              const float* __restrict__ wv,
                                              float* __restrict__ out) {
    extern __shared__ char smA[];
    __shared__ int isLast;
    int tid = threadIdx.x;
    int lane = tid & 31, wid = tid >> 5;
    int blk = blockIdx.x;

#pragma unroll 1
    for (int u = 0; u < U_DIM; u++) {
        unsigned base = (unsigned)u * 512u;

        // ---------- phase 1: gates mma (all 128 blocks: 32 x-blocks x 4 ky) ----
        {
            uint2* bsm = (uint2*)smA;                // 64 KB
            int x = blk & 31, ky = blk >> 5;
            int mt = x * 8 + wid;
            const uint2* bsrc = (ky == 0)
                ? reinterpret_cast<const uint2*>(g_xemb) + u * 8192
                : reinterpret_cast<const uint2*>(g_xt) + ky * 8192;
#pragma unroll 8
            for (int q = 0; q < 32; q++) bsm[q * 256 + tid] = __ldcg(&bsrc[q * 256 + tid]);
            __syncthreads();

            float d[4][4];
#pragma unroll
            for (int n = 0; n < 4; n++)
#pragma unroll
                for (int c = 0; c < 4; c++) d[n][c] = 0.0f;

            const uint4* ap = reinterpret_cast<const uint4*>(g_wt) + (mt * 256 + ky * 64) * 32 + lane;
#pragma unroll 4
            for (int kt = 0; kt < 64; kt++) {
                uint4 a = ap[kt * 32];
#pragma unroll
                for (int n = 0; n < 4; n++) {
                    uint2 b = bsm[(kt * 4 + n) * 32 + lane];
                    mma8(d[n][0], d[n][1], d[n][2], d[n][3], a.x, a.y, a.z, a.w, b.x, b.y);
                }
            }
            int gid = lane >> 2, tig = lane & 3;
            int j0 = mt * 16 + gid;
            float* gp = g_gpart + ky * (G_DIM * 32);
#pragma unroll
            for (int n = 0; n < 4; n++) {
                int bb = n * 8 + 2 * tig;
                *(float2*)&gp[j0 * 32 + bb]       = make_float2(d[n][0], d[n][1]);
                *(float2*)&gp[(j0 + 8) * 32 + bb] = make_float2(d[n][2], d[n][3]);
            }
        }
        gbar(base + 128);

        // ---------- phase 2: fused LSTM + proj partials (blocks 0..63) ---------
        if (blk < 64) {
            float* Wsm = (float*)smA;                // 16 KB
            float* xsm = (float*)(smA + 16384);      // 128*33*4
            int ky = blk >> 3;
            int row0 = (blk & 7) * 64;
            const float* cold = g_c[u & 1];
            float* cnew = g_c[(u + 1) & 1];

#pragma unroll 4
            for (int q = 0; q < 16; q++) {
                int idx = q * 256 + tid;
                int k = idx >> 5, b = idx & 31;
                int ci = ky * 128 + k;
                float gt[4];
#pragma unroll
                for (int gi = 0; gi < 4; gi++) {
                    int j = gi * 1024 + ci;
                    float s = __ldg(&bias[j]);
                    s += __ldcg(&g_gpart[j * 32 + b]);
                    s += __ldcg(&g_gpart[131072 + j * 32 + b]);
                    s += __ldcg(&g_gpart[262144 + j * 32 + b]);
                    s += __ldcg(&g_gpart[393216 + j * 32 + b]);
                    gt[gi] = s;
                }
                float c = __ldcg(&cold[ci * 32 + b]);
                c = sigf(gt[1]) * c + sigf(gt[0]) * tanhf(gt[2]);
                c = fminf(fmaxf(c, -1.0f), 1.0f);
                float h = sigf(gt[3]) * tanhf(c);
                xsm[k * 33 + b] = h;
                if ((blk & 7) == 0) cnew[ci * 32 + b] = c;
            }

            const float* wsrc = Wproj + ky * 128;
            float4 wr[4];
#pragma unroll
            for (int q = 0; q < 4; q++) {
                int idx = q * 256 + tid; int r = idx >> 4, c = (idx & 15) * 4;
                wr[q] = *(const float4*)&wsrc[(row0 + r) * 1024 + c];
            }
            float acc[8];
#pragma unroll
            for (int r = 0; r < 8; r++) acc[r] = 0.0f;

            for (int sub = 0; sub < 2; sub++) {
                __syncthreads();
#pragma unroll
                for (int q = 0; q < 4; q++) {
                    int idx = q * 256 + tid; int r = idx >> 4, c = (idx & 15) * 4;
                    *(float4*)&Wsm[r * 64 + c] = wr[q];
                }
                __syncthreads();
                if (sub < 1) {
#pragma unroll
                    for (int q = 0; q < 4; q++) {
                        int idx = q * 256 + tid; int r = idx >> 4, c = (idx & 15) * 4;
                        wr[q] = *(const float4*)&wsrc[(row0 + r) * 1024 + 64 + c];
                    }
                }
#pragma unroll 4
                for (int kk = 0; kk < 64; kk += 4) {
                    int kb = sub * 64 + kk;
                    float x0 = xsm[kb * 33 + lane];
                    float x1 = xsm[(kb + 1) * 33 + lane];
                    float x2 = xsm[(kb + 2) * 33 + lane];
                    float x3 = xsm[(kb + 3) * 33 + lane];
#pragma unroll
                    for (int r = 0; r < 8; r++) {
                        float4 wv4 = *(const float4*)&Wsm[(wid * 8 + r) * 64 + kk];
                        acc[r] += wv4.x * x0 + wv4.y * x1 + wv4.z * x2 + wv4.w * x3;
                    }
                }
            }
#pragma unroll
            for (int r = 0; r < 8; r++) {
                int j = row0 + wid * 8 + r;
                g_ppart[ky * (O_DIM * 32) + j * 32 + lane] = acc[r];
            }
        }
        gbar(base + 256);

        // ---------- phase 3: state partials (128 blocks: 8 mrow x 16 ksplit) ---
        {
            float* psm  = (float*)smA;               // 32*33 floats
            float* Wsm3 = (float*)(smA + 4224);      // 64*33 floats
            int mrow = blk >> 4, ksp = blk & 15;
            int k0 = ksp * 32;

#pragma unroll
            for (int q = 0; q < 4; q++) {
                int idx = q * 256 + tid; int rl = idx >> 5, b = idx & 31;
                float s = 0.0f;
#pragma unroll
                for (int ky = 0; ky < 8; ky++)
                    s += __ldcg(&g_ppart[ky * (O_DIM * 32) + (k0 + rl) * 32 + b]);
                psm[rl * 33 + b] = s;
                if (mrow == 0) {                     // packed p + masked lstmp out
                    int k = k0 + rl;
                    int kt = 192 + (k >> 3), reg = (k >> 2) & 1, ln = (b & 7) * 4 + (k & 3);
                    g_xt[((kt * 4 + (b >> 3)) * 32 + ln) * 2 + reg] = f2tf(s);
                    out[u * (B_DIM * 1536) + b * 1536 + k] = s * attm[u * 32 + b];
                }
            }
#pragma unroll
            for (int q = 0; q < 8; q++) {
                int idx = q * 256 + tid; int r = idx >> 5, c = idx & 31;
                Wsm3[r * 33 + c] = Wp2s[(mrow * 64 + r) * 512 + k0 + c];
            }
            __syncthreads();

            float acc[8];
#pragma unroll
            for (int r = 0; r < 8; r++) acc[r] = 0.0f;
#pragma unroll 8
            for (int rl = 0; rl < 32; rl++) {
                float x = psm[rl * 33 + lane];
#pragma unroll
                for (int r = 0; r < 8; r++)
                    acc[r] += Wsm3[(wid * 8 + r) * 33 + rl] * x;
            }
#pragma unroll
            for (int r = 0; r < 8; r++) {
                int m = mrow * 64 + wid * 8 + r;
                g_spart[ksp * (M_DIM * 32) + m * 32 + lane] = acc[r];
            }
        }
        gbar(base + 384);

        // ---------- phase 4: scalars + ctx (128 blocks: 32 b x 4 chunks) -------
        {
            float* stt = (float*)smA;                // 512
            float* wvs = (float*)(smA + 2048);       // 512
            float* ssm = (float*)(smA + 4096);       // 125
            int b = blk >> 2, chunk = blk & 3;
            int t0 = chunk * 125;

#pragma unroll
            for (int q = 0; q < 2; q++) {            // state[b][m] from 16 partials
                int m = q * 256 + tid;
                float s = 0.0f;
#pragma unroll
                for (int ksp = 0; ksp < 16; ksp++)
                    s += __ldcg(&g_spart[ksp * (M_DIM * 32) + m * 32 + b]);
                stt[m] = s;
            }
#pragma unroll
            for (int m = tid; m < 512; m += 256) wvs[m] = wv[m];
            __syncthreads();

            for (int t = t0 + wid; t < t0 + 125; t += 8) {
                const __half2* ah2 = (const __half2*)&g_att_hh[(t * 32 + b) * 512];
                float s = 0.0f;
#pragma unroll
                for (int it = 0; it < 8; it++) {
                    int p = lane + it * 32;          // pair index 0..255
                    float2 f = __half22float2(ah2[p]);
                    int m = 2 * p;
                    s += wvs[m]     * fast_tanh(stt[m]     + f.x);
                    s += wvs[m + 1] * fast_tanh(stt[m + 1] + f.y);
                }
#pragma unroll
                for (int off = 16; off; off >>= 1) s += __shfl_xor_sync(0xffffffffu, s, off);
                if (lane == 0) {
                    float bv = (rnn_mask[t * 32 + b] - 1.0f) * 1e10f;
                    ssm[t - t0] = 1.0f / (1.0f + __expf(-(s + bv)));
                }
            }
            __syncthreads();

            // ctx sweep: fp16 data, evict-first (keep L2 for weights/att_h)
            const __half* dbase = g_datah + (size_t)t0 * 32768 + b * 1024 + tid * 4;
            float4 a4 = make_float4(0.f, 0.f, 0.f, 0.f);
            for (int tt = 0; tt < 125; tt += 5) {
                uint2 v[5];
#pragma unroll
                for (int j = 0; j < 5; j++)
                    v[j] = __ldcs((const uint2*)(dbase + (size_t)(tt + j) * 32768));
#pragma unroll
                for (int j = 0; j < 5; j++) {
                    float sc = ssm[tt + j];
                    float2 f0 = __half22float2(*(__half2*)&v[j].x);
                    float2 f1 = __half22float2(*(__half2*)&v[j].y);
                    a4.x += f0.x * sc; a4.y += f0.y * sc;
                    a4.z += f1.x * sc; a4.w += f1.y * sc;
                }
            }
            *(float4*)&g_cpart[chunk * 32768 + b * 1024 + tid * 4] = a4;

            __syncthreads();                         // all stores before fence
            if (tid == 0) {
                __threadfence();
                int old = atomicAdd(&g_ctr[b], 1);
                isLast = (old == u * 4 + 3);         // monotonic per replay
            }
            __syncthreads();
            if (isLast) {
                __threadfence();
                float4 s4 = make_float4(0.f, 0.f, 0.f, 0.f);
#pragma unroll
                for (int p = 0; p < 4; p++) {
                    float4 v = __ldcg((const float4*)&g_cpart[p * 32768 + b * 1024 + tid * 4]);
                    s4.x += v.x; s4.y += v.y; s4.z += v.z; s4.w += v.w;
                }
                float sv[4] = {s4.x, s4.y, s4.z, s4.w};
#pragma unroll
                for (int c = 0; c < 4; c++) {
                    int i = tid * 4 + c;
                    int kt = 64 + (i >> 3), ln = (b & 7) * 4 + (i & 3), reg = (i >> 2) & 1;
                    g_xt[((kt * 4 + (b >> 3)) * 32 + ln) * 2 + reg] = f2tf(sv[c]);
                    out[u * (B_DIM * 1536) + b * 1536 + 512 + i] = sv[c] * attm[u * 32 + b];
                }
            }
        }
        gbar(base + 512);   // g_xt complete before next step's gates
    }
}

// ---------------- launch --------------------------------------------------------
extern "C" void kernel_launch(void* const* d_in, const int* in_sizes, int n_in,
                              void* d_out, int out_size) {
    const float* data      = (const float*)d_in[0];
    const float* att_mask  = (const float*)d_in[1];
    const int*   att_label = (const int*)  d_in[2];
    const float* rnn_mask  = (const float*)d_in[3];
    const float* embW      = (const float*)d_in[4];
    const float* Wi2h      = (const float*)d_in[5];
    const float* Wp2s      = (const float*)d_in[6];
    const float* wv        = (const float*)d_in[7];
    const float* Wx        = (const float*)d_in[8];
    const float* Wp        = (const float*)d_in[9];
    const float* bias      = (const float*)d_in[10];
    const float* Wproj     = (const float*)d_in[11];
    float* out = (float*)d_out;

    cudaFuncSetAttribute(k_mega, cudaFuncAttributeMaxDynamicSharedMemorySize, 65536);

    k_wpack<<<32768, 256>>>(Wx, Wp);
    k_dpack<<<64000, 256>>>(data);
    k_hpack<<<64000, 256>>>(data);
    k_bpack<<<2048, 256>>>(Wi2h);
    k_embed<<<6400, 256>>>(att_label, embW);
    k_atth<<<dim3(125, 4), 512>>>();
    k_init<<<256, 256>>>();

    k_mega<<<128, 256, 65536>>>(Wproj, bias, Wp2s, att_mask,
                                rnn_mask, wv, out);
}